// round 10
// baseline (speedup 1.0000x reference)
#include <cuda_runtime.h>

#define Bc 4
#define Cc 64
#define Ec 8
#define Nn 4096
#define Ti 256
#define L2E 1.4426950408889634f

typedef unsigned long long ull;

// ---- static scratch (no allocations allowed) ----
// f/h stored pair-replicated: d_f2[b][e2][i] = { (f[2e2,i],f[2e2,i]), (f[2e2+1,i],f[2e2+1,i]) }
__device__ __align__(16) ulonglong2 d_f2[Bc * 4 * Nn];
__device__ __align__(16) ulonglong2 d_h2[Bc * 4 * Nn];
__device__ __align__(16) float d_g[Bc * Ec * Nn];

// ---- packed f32x2 helpers (Blackwell) ----
__device__ __forceinline__ ull pk2(float a, float b) {
    ull r; asm("mov.b64 %0,{%1,%2};" : "=l"(r) : "f"(a), "f"(b)); return r;
}
__device__ __forceinline__ float2 up2(ull v) {
    float2 r; asm("mov.b64 {%0,%1},%2;" : "=f"(r.x), "=f"(r.y) : "l"(v)); return r;
}
__device__ __forceinline__ ull fma2(ull a, ull b, ull c) {
    ull d; asm("fma.rn.f32x2 %0,%1,%2,%3;" : "=l"(d) : "l"(a), "l"(b), "l"(c)); return d;
}
__device__ __forceinline__ float ex2(float x) {
    float r; asm("ex2.approx.f32 %0,%1;" : "=f"(r) : "f"(x)); return r;
}

// ============================================================
// Kernel A: projections. 128 CTAs x 128 threads -> every SM busy.
// Writes g plain, f/h pair-replicated ulonglong2.
// ============================================================
__global__ __launch_bounds__(128) void proj_kernel(
    const float* __restrict__ x,
    const float* __restrict__ Wk, const float* __restrict__ bk,
    const float* __restrict__ Wq, const float* __restrict__ bq,
    const float* __restrict__ Wv, const float* __restrict__ bv)
{
    __shared__ float Wks[Ec * Cc], Wqs[Ec * Cc], Wvs[Ec * Cc];
    __shared__ float bks[Ec], bqs[Ec], bvs[Ec];
    const int t = threadIdx.x;
    const int b = blockIdx.y;
    const int n = blockIdx.x * 128 + t;
    for (int i = t; i < Ec * Cc; i += 128) { Wks[i] = Wk[i]; Wqs[i] = Wq[i]; Wvs[i] = Wv[i]; }
    if (t < Ec) { bks[t] = bk[t]; bqs[t] = bq[t]; bvs[t] = bv[t]; }
    __syncthreads();

    float xc[Cc];
    const float* xb = x + (size_t)b * Cc * Nn + n;
#pragma unroll
    for (int c = 0; c < Cc; c++) xc[c] = xb[(size_t)c * Nn];

    float fv[Ec], gv[Ec], hv[Ec];
#pragma unroll
    for (int e = 0; e < Ec; e++) {
        float af = bks[e], ag = bqs[e], av = bvs[e];
#pragma unroll
        for (int c = 0; c < Cc; c++) {
            float xv = xc[c];
            af = fmaf(Wks[e * Cc + c], xv, af);
            ag = fmaf(Wqs[e * Cc + c], xv, ag);
            av = fmaf(Wvs[e * Cc + c], xv, av);
        }
        fv[e] = af; gv[e] = ag; hv[e] = av;
    }
#pragma unroll
    for (int e = 0; e < Ec; e++) d_g[(b * Ec + e) * Nn + n] = gv[e];
#pragma unroll
    for (int e2 = 0; e2 < 4; e2++) {
        ulonglong2 rf, rh;
        rf.x = pk2(fv[2 * e2], fv[2 * e2]);     rf.y = pk2(fv[2 * e2 + 1], fv[2 * e2 + 1]);
        rh.x = pk2(hv[2 * e2], hv[2 * e2]);     rh.y = pk2(hv[2 * e2 + 1], hv[2 * e2 + 1]);
        d_f2[(b * 4 + e2) * Nn + n] = rf;
        d_h2[(b * 4 + e2) * Nn + n] = rh;
    }
}

// ============================================================
// Kernel B: attention + fused output projection.
// CTA = (batch, 128-column block). 256 threads, 8 warps.
// Each lane owns 4 consecutive columns; warp spans all 128 columns;
// the 8 warps split the i-range.
//   pass1: l[j] = sum_i exp(f_i . g_j)        -> lr[j] = -log2 l[j]
//   pass2: beta[i,j] = ex2(s*log2e + lr[j])   (STG.128 per lane)
//          v[e,j] += h[e,i] * beta
//   epilogue: y = leaky(gamma*(Wo v + bo) + x)
// ============================================================
struct __align__(16) Sm {
    union {
        struct { ulonglong2 fs[4][Ti]; ulonglong2 hs[4][Ti]; } tiles;  // 32 KB
        float vsc[8][8][128];                                          // 32 KB (epilogue)
    } u;
    float lred[8][128];   // warp partials for l; reused as final v[e][j]
    float lr[128];        // -log2(l[j])
    float Wos[Cc * Ec];
    float bos[Cc];
};

__global__ __launch_bounds__(256, 1) void attn_kernel(
    const float* __restrict__ x,
    const float* __restrict__ Wo, const float* __restrict__ bo,
    const float* __restrict__ gamma,
    float* __restrict__ out_y, float* __restrict__ out_beta)
{
    __shared__ Sm sm;

    const int tid  = threadIdx.x;
    const int lane = tid & 31;
    const int wp   = tid >> 5;
    const int b    = blockIdx.y;
    const int jbase = blockIdx.x * 128;
    const int j0   = jbase + lane * 4;

    // preload output-proj weights (used only in epilogue)
    for (int i = tid; i < Cc * Ec; i += 256) sm.Wos[i] = Wo[i];
    if (tid < Cc) sm.bos[tid] = bo[tid];

    // g for this lane's 4 columns, packed as (j0,j1) and (j2,j3) pairs
    ull gA[Ec], gB[Ec];
    const float* gb = d_g + b * Ec * Nn;
#pragma unroll
    for (int e = 0; e < Ec; e++) {
        float4 g4 = *(const float4*)(gb + e * Nn + j0);
        gA[e] = pk2(g4.x, g4.y);
        gB[e] = pk2(g4.z, g4.w);
    }

    const ulonglong2* fb = d_f2 + b * 4 * Nn;
    const ulonglong2* hb = d_h2 + b * 4 * Nn;

    // ---------------- pass 1: column sums ----------------
    float ls0 = 0.f, ls1 = 0.f, ls2 = 0.f, ls3 = 0.f;
    for (int t0 = 0; t0 < Nn; t0 += Ti) {
        __syncthreads();
#pragma unroll
        for (int e2 = 0; e2 < 4; e2++)
            sm.u.tiles.fs[e2][tid] = fb[e2 * Nn + t0 + tid];
        __syncthreads();
#pragma unroll
        for (int k = 0; k < 8; k++) {
            const int ib = k * 32 + wp * 4;
#pragma unroll
            for (int c = 0; c < 4; c++) {
                const int i = ib + c;
                ull s01 = 0ULL, s23 = 0ULL;
#pragma unroll
                for (int e2 = 0; e2 < 4; e2++) {
                    ulonglong2 fv = sm.u.tiles.fs[e2][i];
                    s01 = fma2(fv.x, gA[2 * e2], s01);
                    s01 = fma2(fv.y, gA[2 * e2 + 1], s01);
                    s23 = fma2(fv.x, gB[2 * e2], s23);
                    s23 = fma2(fv.y, gB[2 * e2 + 1], s23);
                }
                float2 a = up2(s01), d2 = up2(s23);
                ls0 += ex2(a.x * L2E);
                ls1 += ex2(a.y * L2E);
                ls2 += ex2(d2.x * L2E);
                ls3 += ex2(d2.y * L2E);
            }
        }
    }
    __syncthreads();
    *(float4*)&sm.lred[wp][lane * 4] = make_float4(ls0, ls1, ls2, ls3);
    __syncthreads();
    if (tid < 128) {
        float s = 0.f;
#pragma unroll
        for (int w = 0; w < 8; w++) s += sm.lred[w][tid];
        sm.lr[tid] = -__log2f(s);
    }
    __syncthreads();
    const float lr0 = sm.lr[lane * 4 + 0];
    const float lr1 = sm.lr[lane * 4 + 1];
    const float lr2 = sm.lr[lane * 4 + 2];
    const float lr3 = sm.lr[lane * 4 + 3];

    // ---------------- pass 2: beta + v ----------------
    ull vA[Ec], vB[Ec];
#pragma unroll
    for (int e = 0; e < Ec; e++) { vA[e] = 0ULL; vB[e] = 0ULL; }
    float* bout = out_beta + (size_t)b * Nn * Nn + j0;

    for (int t0 = 0; t0 < Nn; t0 += Ti) {
        __syncthreads();
#pragma unroll
        for (int e2 = 0; e2 < 4; e2++) {
            sm.u.tiles.fs[e2][tid] = fb[e2 * Nn + t0 + tid];
            sm.u.tiles.hs[e2][tid] = hb[e2 * Nn + t0 + tid];
        }
        __syncthreads();
#pragma unroll
        for (int k = 0; k < 8; k++) {
            const int ib = k * 32 + wp * 4;
#pragma unroll
            for (int c = 0; c < 4; c++) {
                const int i = ib + c;
                ull s01 = 0ULL, s23 = 0ULL;
#pragma unroll
                for (int e2 = 0; e2 < 4; e2++) {
                    ulonglong2 fv = sm.u.tiles.fs[e2][i];
                    s01 = fma2(fv.x, gA[2 * e2], s01);
                    s01 = fma2(fv.y, gA[2 * e2 + 1], s01);
                    s23 = fma2(fv.x, gB[2 * e2], s23);
                    s23 = fma2(fv.y, gB[2 * e2 + 1], s23);
                }
                float2 a = up2(s01), d2 = up2(s23);
                float b0 = ex2(fmaf(a.x, L2E, lr0));
                float b1 = ex2(fmaf(a.y, L2E, lr1));
                float b2v = ex2(fmaf(d2.x, L2E, lr2));
                float b3 = ex2(fmaf(d2.y, L2E, lr3));
                *(float4*)(bout + (size_t)(t0 + i) * Nn) = make_float4(b0, b1, b2v, b3);
                ull b01 = pk2(b0, b1), b23 = pk2(b2v, b3);
#pragma unroll
                for (int e2 = 0; e2 < 4; e2++) {
                    ulonglong2 hv = sm.u.tiles.hs[e2][i];
                    vA[2 * e2]     = fma2(hv.x, b01, vA[2 * e2]);
                    vA[2 * e2 + 1] = fma2(hv.y, b01, vA[2 * e2 + 1]);
                    vB[2 * e2]     = fma2(hv.x, b23, vB[2 * e2]);
                    vB[2 * e2 + 1] = fma2(hv.y, b23, vB[2 * e2 + 1]);
                }
            }
        }
    }

    // ---------------- reduce v across warps ----------------
    __syncthreads();   // tiles no longer needed; vsc overlays them
#pragma unroll
    for (int e = 0; e < Ec; e++) {
        float2 a = up2(vA[e]), c2 = up2(vB[e]);
        *(float4*)&sm.u.vsc[wp][e][lane * 4] = make_float4(a.x, a.y, c2.x, c2.y);
    }
    __syncthreads();
    for (int m = tid; m < Ec * 128; m += 256) {
        const int e = m >> 7, jl = m & 127;
        float s = 0.f;
#pragma unroll
        for (int w = 0; w < 8; w++) s += sm.u.vsc[w][e][jl];
        sm.lred[e][jl] = s;   // final v[e][jl]
    }
    __syncthreads();

    // ---------------- fused output projection ----------------
    const float gm = *gamma;
    const int jl = tid & 127;
    const int ch = (tid >> 7) * 32;
    const float* xb = x + (size_t)b * Cc * Nn + jbase + jl;
    float* yb = out_y + (size_t)b * Cc * Nn + jbase + jl;
    float ve[Ec];
#pragma unroll
    for (int e = 0; e < Ec; e++) ve[e] = sm.lred[e][jl];
#pragma unroll
    for (int cc = 0; cc < 32; cc++) {
        const int c = ch + cc;
        float o = sm.bos[c];
#pragma unroll
        for (int e = 0; e < Ec; e++) o = fmaf(sm.Wos[c * Ec + e], ve[e], o);
        float y = fmaf(gm, o, xb[(size_t)c * Nn]);
        yb[(size_t)c * Nn] = (y >= 0.f) ? y : 0.01f * y;
    }
}

extern "C" void kernel_launch(void* const* d_in, const int* in_sizes, int n_in,
                              void* d_out, int out_size)
{
    const float* x     = (const float*)d_in[0];
    const float* Wk    = (const float*)d_in[1];
    const float* bk    = (const float*)d_in[2];
    const float* Wq    = (const float*)d_in[3];
    const float* bq    = (const float*)d_in[4];
    const float* Wv    = (const float*)d_in[5];
    const float* bv    = (const float*)d_in[6];
    const float* Wo    = (const float*)d_in[7];
    const float* bo    = (const float*)d_in[8];
    const float* gamma = (const float*)d_in[9];

    float* out_y    = (float*)d_out;                 // [B,C,H,W] first
    float* out_beta = out_y + (size_t)Bc * Cc * Nn;  // then [B,N,N]

    proj_kernel<<<dim3(Nn / 128, Bc), 128>>>(x, Wk, bk, Wq, bq, Wv, bv);
    attn_kernel<<<dim3(Nn / 128, Bc), 256>>>(x, Wo, bo, gamma, out_y, out_beta);
}

// round 11
// speedup vs baseline: 1.0041x; 1.0041x over previous
#include <cuda_runtime.h>

#define Bc 4
#define Cc 64
#define Ec 8
#define Nn 4096
#define Ti 256
#define L2E 1.4426950408889634f

typedef unsigned long long ull;

// ---- static scratch (no allocations allowed) ----
// f/h stored pair-replicated: d_f2[b][e2][i] = { (f[2e2,i],f[2e2,i]), (f[2e2+1,i],f[2e2+1,i]) }
__device__ __align__(16) ulonglong2 d_f2[Bc * 4 * Nn];
__device__ __align__(16) ulonglong2 d_h2[Bc * 4 * Nn];
__device__ __align__(16) float d_g[Bc * Ec * Nn];

// ---- packed f32x2 helpers (Blackwell) ----
__device__ __forceinline__ ull pk2(float a, float b) {
    ull r; asm("mov.b64 %0,{%1,%2};" : "=l"(r) : "f"(a), "f"(b)); return r;
}
__device__ __forceinline__ float2 up2(ull v) {
    float2 r; asm("mov.b64 {%0,%1},%2;" : "=f"(r.x), "=f"(r.y) : "l"(v)); return r;
}
__device__ __forceinline__ ull fma2(ull a, ull b, ull c) {
    ull d; asm("fma.rn.f32x2 %0,%1,%2,%3;" : "=l"(d) : "l"(a), "l"(b), "l"(c)); return d;
}
__device__ __forceinline__ float ex2(float x) {
    float r; asm("ex2.approx.f32 %0,%1;" : "=f"(r) : "f"(x)); return r;
}

// ============================================================
// Kernel A: projections. 128 CTAs x 128 threads -> every SM busy.
// Writes g plain, f/h pair-replicated ulonglong2.
// ============================================================
__global__ __launch_bounds__(128) void proj_kernel(
    const float* __restrict__ x,
    const float* __restrict__ Wk, const float* __restrict__ bk,
    const float* __restrict__ Wq, const float* __restrict__ bq,
    const float* __restrict__ Wv, const float* __restrict__ bv)
{
    __shared__ float Wks[Ec * Cc], Wqs[Ec * Cc], Wvs[Ec * Cc];
    __shared__ float bks[Ec], bqs[Ec], bvs[Ec];
    const int t = threadIdx.x;
    const int b = blockIdx.y;
    const int n = blockIdx.x * 128 + t;
    for (int i = t; i < Ec * Cc; i += 128) { Wks[i] = Wk[i]; Wqs[i] = Wq[i]; Wvs[i] = Wv[i]; }
    if (t < Ec) { bks[t] = bk[t]; bqs[t] = bq[t]; bvs[t] = bv[t]; }
    __syncthreads();

    float xc[Cc];
    const float* xb = x + (size_t)b * Cc * Nn + n;
#pragma unroll
    for (int c = 0; c < Cc; c++) xc[c] = xb[(size_t)c * Nn];

    float fv[Ec], gv[Ec], hv[Ec];
#pragma unroll
    for (int e = 0; e < Ec; e++) {
        float af = bks[e], ag = bqs[e], av = bvs[e];
#pragma unroll
        for (int c = 0; c < Cc; c++) {
            float xv = xc[c];
            af = fmaf(Wks[e * Cc + c], xv, af);
            ag = fmaf(Wqs[e * Cc + c], xv, ag);
            av = fmaf(Wvs[e * Cc + c], xv, av);
        }
        fv[e] = af; gv[e] = ag; hv[e] = av;
    }
#pragma unroll
    for (int e = 0; e < Ec; e++) d_g[(b * Ec + e) * Nn + n] = gv[e];
#pragma unroll
    for (int e2 = 0; e2 < 4; e2++) {
        ulonglong2 rf, rh;
        rf.x = pk2(fv[2 * e2], fv[2 * e2]);     rf.y = pk2(fv[2 * e2 + 1], fv[2 * e2 + 1]);
        rh.x = pk2(hv[2 * e2], hv[2 * e2]);     rh.y = pk2(hv[2 * e2 + 1], hv[2 * e2 + 1]);
        d_f2[(b * 4 + e2) * Nn + n] = rf;
        d_h2[(b * 4 + e2) * Nn + n] = rh;
    }
}

// ============================================================
// Kernel B: attention + fused output projection.
// CTA = (batch, 128-column block). 256 threads, 8 warps.
// Each lane owns 4 consecutive columns; warp spans all 128 columns;
// the 8 warps split the i-range.
//   pass1: l[j] = sum_i exp(f_i . g_j)        -> lr[j] = -log2 l[j]
//   pass2: beta[i,j] = ex2(s*log2e + lr[j])   (STG.128 per lane)
//          v[e,j] += h[e,i] * beta
//   epilogue: y = leaky(gamma*(Wo v + bo) + x)
// ============================================================
struct __align__(16) Sm {
    union {
        struct { ulonglong2 fs[4][Ti]; ulonglong2 hs[4][Ti]; } tiles;  // 32 KB
        float vsc[8][8][128];                                          // 32 KB (epilogue)
    } u;
    float lred[8][128];   // warp partials for l; reused as final v[e][j]
    float lr[128];        // -log2(l[j])
    float Wos[Cc * Ec];
    float bos[Cc];
};

__global__ __launch_bounds__(256, 1) void attn_kernel(
    const float* __restrict__ x,
    const float* __restrict__ Wo, const float* __restrict__ bo,
    const float* __restrict__ gamma,
    float* __restrict__ out_y, float* __restrict__ out_beta)
{
    __shared__ Sm sm;

    const int tid  = threadIdx.x;
    const int lane = tid & 31;
    const int wp   = tid >> 5;
    const int b    = blockIdx.y;
    const int jbase = blockIdx.x * 128;
    const int j0   = jbase + lane * 4;

    // preload output-proj weights (used only in epilogue)
    for (int i = tid; i < Cc * Ec; i += 256) sm.Wos[i] = Wo[i];
    if (tid < Cc) sm.bos[tid] = bo[tid];

    // g for this lane's 4 columns, packed as (j0,j1) and (j2,j3) pairs
    ull gA[Ec], gB[Ec];
    const float* gb = d_g + b * Ec * Nn;
#pragma unroll
    for (int e = 0; e < Ec; e++) {
        float4 g4 = *(const float4*)(gb + e * Nn + j0);
        gA[e] = pk2(g4.x, g4.y);
        gB[e] = pk2(g4.z, g4.w);
    }

    const ulonglong2* fb = d_f2 + b * 4 * Nn;
    const ulonglong2* hb = d_h2 + b * 4 * Nn;

    // ---------------- pass 1: column sums ----------------
    float ls0 = 0.f, ls1 = 0.f, ls2 = 0.f, ls3 = 0.f;
    for (int t0 = 0; t0 < Nn; t0 += Ti) {
        __syncthreads();
#pragma unroll
        for (int e2 = 0; e2 < 4; e2++)
            sm.u.tiles.fs[e2][tid] = fb[e2 * Nn + t0 + tid];
        __syncthreads();
#pragma unroll
        for (int k = 0; k < 8; k++) {
            const int ib = k * 32 + wp * 4;
#pragma unroll
            for (int c = 0; c < 4; c++) {
                const int i = ib + c;
                ull s01 = 0ULL, s23 = 0ULL;
#pragma unroll
                for (int e2 = 0; e2 < 4; e2++) {
                    ulonglong2 fv = sm.u.tiles.fs[e2][i];
                    s01 = fma2(fv.x, gA[2 * e2], s01);
                    s01 = fma2(fv.y, gA[2 * e2 + 1], s01);
                    s23 = fma2(fv.x, gB[2 * e2], s23);
                    s23 = fma2(fv.y, gB[2 * e2 + 1], s23);
                }
                float2 a = up2(s01), d2 = up2(s23);
                ls0 += ex2(a.x * L2E);
                ls1 += ex2(a.y * L2E);
                ls2 += ex2(d2.x * L2E);
                ls3 += ex2(d2.y * L2E);
            }
        }
    }
    __syncthreads();
    *(float4*)&sm.lred[wp][lane * 4] = make_float4(ls0, ls1, ls2, ls3);
    __syncthreads();
    if (tid < 128) {
        float s = 0.f;
#pragma unroll
        for (int w = 0; w < 8; w++) s += sm.lred[w][tid];
        sm.lr[tid] = -__log2f(s);
    }
    __syncthreads();
    const float lr0 = sm.lr[lane * 4 + 0];
    const float lr1 = sm.lr[lane * 4 + 1];
    const float lr2 = sm.lr[lane * 4 + 2];
    const float lr3 = sm.lr[lane * 4 + 3];

    // ---------------- pass 2: beta + v ----------------
    ull vA[Ec], vB[Ec];
#pragma unroll
    for (int e = 0; e < Ec; e++) { vA[e] = 0ULL; vB[e] = 0ULL; }
    float* bout = out_beta + (size_t)b * Nn * Nn + j0;

    for (int t0 = 0; t0 < Nn; t0 += Ti) {
        __syncthreads();
#pragma unroll
        for (int e2 = 0; e2 < 4; e2++) {
            sm.u.tiles.fs[e2][tid] = fb[e2 * Nn + t0 + tid];
            sm.u.tiles.hs[e2][tid] = hb[e2 * Nn + t0 + tid];
        }
        __syncthreads();
#pragma unroll
        for (int k = 0; k < 8; k++) {
            const int ib = k * 32 + wp * 4;
#pragma unroll
            for (int c = 0; c < 4; c++) {
                const int i = ib + c;
                ull s01 = 0ULL, s23 = 0ULL;
#pragma unroll
                for (int e2 = 0; e2 < 4; e2++) {
                    ulonglong2 fv = sm.u.tiles.fs[e2][i];
                    s01 = fma2(fv.x, gA[2 * e2], s01);
                    s01 = fma2(fv.y, gA[2 * e2 + 1], s01);
                    s23 = fma2(fv.x, gB[2 * e2], s23);
                    s23 = fma2(fv.y, gB[2 * e2 + 1], s23);
                }
                float2 a = up2(s01), d2 = up2(s23);
                float b0 = ex2(fmaf(a.x, L2E, lr0));
                float b1 = ex2(fmaf(a.y, L2E, lr1));
                float b2v = ex2(fmaf(d2.x, L2E, lr2));
                float b3 = ex2(fmaf(d2.y, L2E, lr3));
                *(float4*)(bout + (size_t)(t0 + i) * Nn) = make_float4(b0, b1, b2v, b3);
                ull b01 = pk2(b0, b1), b23 = pk2(b2v, b3);
#pragma unroll
                for (int e2 = 0; e2 < 4; e2++) {
                    ulonglong2 hv = sm.u.tiles.hs[e2][i];
                    vA[2 * e2]     = fma2(hv.x, b01, vA[2 * e2]);
                    vA[2 * e2 + 1] = fma2(hv.y, b01, vA[2 * e2 + 1]);
                    vB[2 * e2]     = fma2(hv.x, b23, vB[2 * e2]);
                    vB[2 * e2 + 1] = fma2(hv.y, b23, vB[2 * e2 + 1]);
                }
            }
        }
    }

    // ---------------- reduce v across warps ----------------
    __syncthreads();   // tiles no longer needed; vsc overlays them
#pragma unroll
    for (int e = 0; e < Ec; e++) {
        float2 a = up2(vA[e]), c2 = up2(vB[e]);
        *(float4*)&sm.u.vsc[wp][e][lane * 4] = make_float4(a.x, a.y, c2.x, c2.y);
    }
    __syncthreads();
    for (int m = tid; m < Ec * 128; m += 256) {
        const int e = m >> 7, jl = m & 127;
        float s = 0.f;
#pragma unroll
        for (int w = 0; w < 8; w++) s += sm.u.vsc[w][e][jl];
        sm.lred[e][jl] = s;   // final v[e][jl]
    }
    __syncthreads();

    // ---------------- fused output projection ----------------
    const float gm = *gamma;
    const int jl = tid & 127;
    const int ch = (tid >> 7) * 32;
    const float* xb = x + (size_t)b * Cc * Nn + jbase + jl;
    float* yb = out_y + (size_t)b * Cc * Nn + jbase + jl;
    float ve[Ec];
#pragma unroll
    for (int e = 0; e < Ec; e++) ve[e] = sm.lred[e][jl];
#pragma unroll
    for (int cc = 0; cc < 32; cc++) {
        const int c = ch + cc;
        float o = sm.bos[c];
#pragma unroll
        for (int e = 0; e < Ec; e++) o = fmaf(sm.Wos[c * Ec + e], ve[e], o);
        float y = fmaf(gm, o, xb[(size_t)c * Nn]);
        yb[(size_t)c * Nn] = (y >= 0.f) ? y : 0.01f * y;
    }
}

extern "C" void kernel_launch(void* const* d_in, const int* in_sizes, int n_in,
                              void* d_out, int out_size)
{
    const float* x     = (const float*)d_in[0];
    const float* Wk    = (const float*)d_in[1];
    const float* bk    = (const float*)d_in[2];
    const float* Wq    = (const float*)d_in[3];
    const float* bq    = (const float*)d_in[4];
    const float* Wv    = (const float*)d_in[5];
    const float* bv    = (const float*)d_in[6];
    const float* Wo    = (const float*)d_in[7];
    const float* bo    = (const float*)d_in[8];
    const float* gamma = (const float*)d_in[9];

    float* out_y    = (float*)d_out;                 // [B,C,H,W] first
    float* out_beta = out_y + (size_t)Bc * Cc * Nn;  // then [B,N,N]

    proj_kernel<<<dim3(Nn / 128, Bc), 128>>>(x, Wk, bk, Wq, bq, Wv, bv);
    attn_kernel<<<dim3(Nn / 128, Bc), 256>>>(x, Wo, bo, gamma, out_y, out_beta);
}